// round 8
// baseline (speedup 1.0000x reference)
#include <cuda_runtime.h>
#include <math.h>

#define B_SZ 2048
#define T_SZ 200
#define NB   16

// ---------------- device scratch (no runtime allocation allowed) ----------------
__device__ __align__(16) float g_l1_whhT[2][128*512];
__device__ __align__(16) float g_l1_wih [2][512];
__device__ __align__(16) float g_l1_b   [2][512];
__device__ __align__(16) float g_l2_wihT[2][256*512];
__device__ __align__(16) float g_l2_whhT[2][128*512];
__device__ __align__(16) float g_l2_b   [2][512];
__device__ __align__(16) float g_fc1_wT[256*256];
__device__ __align__(16) float g_fc2_wT[256*64];
__device__ __align__(16) float g_g1_whhT[128*512];
__device__ __align__(16) float g_g1_wih[512];
__device__ __align__(16) float g_g1_bih[512];
__device__ __align__(16) float g_g1_bhh[512];
__device__ __align__(16) float g_g2_wihT[128*160];
__device__ __align__(16) float g_g2_whhT[50*160];
__device__ __align__(16) float g_h1out[(size_t)T_SZ*B_SZ*256]; // [t][b][256] fwd|bwd
__device__ __align__(16) float g_hn[4][B_SZ*128];              // L1 f/b, L2 f/b final h
__device__ __align__(16) float g_hidden[B_SZ*128];             // decoder h1 init

__device__ __forceinline__ float sigf(float x){ return 1.0f/(1.0f + expf(-x)); }

// ---------------- weight permutation ----------------
// Gate-quad layout: transposed weight column (h*4+q) = original gate row (q*H+h),
// so one thread owns the full (i,f,g,o)/(r,z,n) quad of hidden index h.
__global__ void k_prep(
    const float* __restrict__ l1_wih_f, const float* __restrict__ l1_whh_f, const float* __restrict__ l1_b_f,
    const float* __restrict__ l1_wih_b, const float* __restrict__ l1_whh_b, const float* __restrict__ l1_b_b,
    const float* __restrict__ l2_wih_f, const float* __restrict__ l2_whh_f, const float* __restrict__ l2_b_f,
    const float* __restrict__ l2_wih_b, const float* __restrict__ l2_whh_b, const float* __restrict__ l2_b_b,
    const float* __restrict__ fc1_w, const float* __restrict__ fc2_w,
    const float* __restrict__ g1_wih, const float* __restrict__ g1_whh,
    const float* __restrict__ g1_bih, const float* __restrict__ g1_bhh,
    const float* __restrict__ g2_wih, const float* __restrict__ g2_whh)
{
    const int idx = blockIdx.x*blockDim.x + threadIdx.x;
    const int stride = gridDim.x*blockDim.x;

    for (int i=idx; i<2*128*512; i+=stride){          // L1 whh^T
        int dir=i>>16, r=i&65535, k=r>>9, col=r&511, h=col>>2, q=col&3;
        const float* s = dir ? l1_whh_b : l1_whh_f;
        g_l1_whhT[dir][r] = s[(q*128+h)*128 + k];
    }
    for (int i=idx; i<2*128*512; i+=stride){          // L2 whh^T
        int dir=i>>16, r=i&65535, k=r>>9, col=r&511, h=col>>2, q=col&3;
        const float* s = dir ? l2_whh_b : l2_whh_f;
        g_l2_whhT[dir][r] = s[(q*128+h)*128 + k];
    }
    for (int i=idx; i<2*256*512; i+=stride){          // L2 wih^T (k<256)
        int dir=i>>17, r=i&131071, k=r>>9, col=r&511, h=col>>2, q=col&3;
        const float* s = dir ? l2_wih_b : l2_wih_f;
        g_l2_wihT[dir][r] = s[(q*128+h)*256 + k];
    }
    for (int i=idx; i<2*512; i+=stride){              // L1/L2 small vectors
        int dir=i>>9, col=i&511, h=col>>2, q=col&3, g=q*128+h;
        g_l1_wih[dir][col] = (dir ? l1_wih_b : l1_wih_f)[g];
        g_l1_b  [dir][col] = (dir ? l1_b_b   : l1_b_f  )[g];
        g_l2_b  [dir][col] = (dir ? l2_b_b   : l2_b_f  )[g];
    }
    for (int i=idx; i<256*256; i+=stride){            // fc1^T
        int c=i>>8, j=i&255;
        g_fc1_wT[i] = fc1_w[j*256+c];
    }
    for (int i=idx; i<256*64; i+=stride){             // fc2^T
        int c=i>>6, j=i&63;
        g_fc2_wT[i] = fc2_w[j*256+c];
    }
    for (int i=idx; i<128*512; i+=stride){            // g1 whh^T (3 gates, q=3 padded 0)
        int k=i>>9, col=i&511, h=col>>2, q=col&3;
        g_g1_whhT[i] = (q<3) ? g1_whh[(q*128+h)*128 + k] : 0.0f;
    }
    for (int i=idx; i<512; i+=stride){                // g1 vectors
        int h=i>>2, q=i&3;
        g_g1_wih[i] = (q<3) ? g1_wih[q*128+h] : 0.0f;
        g_g1_bih[i] = (q<3) ? g1_bih[q*128+h] : 0.0f;
        g_g1_bhh[i] = (q<3) ? g1_bhh[q*128+h] : 0.0f;
    }
    for (int i=idx; i<128*160; i+=stride){            // g2 wih^T
        int k=i/160, g=i%160;
        g_g2_wihT[i] = (g<150) ? g2_wih[g*128+k] : 0.0f;
    }
    for (int i=idx; i<50*160; i+=stride){             // g2 whh^T
        int k=i/160, g=i%160;
        g_g2_whhT[i] = (g<150) ? g2_whh[g*50+k] : 0.0f;
    }
}

// ---------------- BiLSTM layer 1 (input dim 1) ----------------
__global__ void __launch_bounds__(128) k_lstm1(const float* __restrict__ edge)
{
    const int dir = blockIdx.y;
    const int b0  = blockIdx.x * NB;
    const int hh  = threadIdx.x;

    __shared__ float sh_x[NB][T_SZ];
    __shared__ float sh_h[NB][128];

    for (int i = hh; i < NB*T_SZ; i += 128){
        int b = i / T_SZ, t = i % T_SZ;
        sh_x[b][t] = edge[(b0+b)*T_SZ + t];
    }
    #pragma unroll
    for (int b=0;b<NB;b++) sh_h[b][hh] = 0.0f;
    float c[NB];
    #pragma unroll
    for (int b=0;b<NB;b++) c[b] = 0.0f;

    const float4* __restrict__ W = (const float4*)g_l1_whhT[dir];
    const float4 wi = ((const float4*)g_l1_wih[dir])[hh];
    const float4 bb = ((const float4*)g_l1_b[dir])[hh];
    __syncthreads();

    for (int s=0; s<T_SZ; s++){
        const int t = dir ? (T_SZ-1-s) : s;
        float4 acc[NB];
        #pragma unroll
        for (int b=0;b<NB;b++){
            float xv = sh_x[b][t];
            acc[b].x = fmaf(xv, wi.x, bb.x);
            acc[b].y = fmaf(xv, wi.y, bb.y);
            acc[b].z = fmaf(xv, wi.z, bb.z);
            acc[b].w = fmaf(xv, wi.w, bb.w);
        }
        #pragma unroll 2
        for (int k=0;k<128;k++){
            float4 w = W[k*128 + hh];
            #pragma unroll
            for (int b=0;b<NB;b++){
                float hv = sh_h[b][k];
                acc[b].x = fmaf(hv, w.x, acc[b].x);
                acc[b].y = fmaf(hv, w.y, acc[b].y);
                acc[b].z = fmaf(hv, w.z, acc[b].z);
                acc[b].w = fmaf(hv, w.w, acc[b].w);
            }
        }
        __syncthreads();
        float* outp = g_h1out + (size_t)t*(B_SZ*256) + (size_t)b0*256 + dir*128 + hh;
        #pragma unroll
        for (int b=0;b<NB;b++){
            float ig = sigf(acc[b].x);
            float fg = sigf(acc[b].y);
            float gg = tanhf(acc[b].z);
            float og = sigf(acc[b].w);
            c[b] = fmaf(fg, c[b], ig*gg);
            float h = og * tanhf(c[b]);
            sh_h[b][hh] = h;
            outp[b*256] = h;
        }
        __syncthreads();
    }
    #pragma unroll
    for (int b=0;b<NB;b++) g_hn[dir][(b0+b)*128 + hh] = sh_h[b][hh];
}

// ---------------- BiLSTM layer 2 (input dim 256, projection fused) ----------------
__global__ void __launch_bounds__(128) k_lstm2()
{
    const int dir = blockIdx.y;
    const int b0  = blockIdx.x * NB;
    const int hh  = threadIdx.x;

    __shared__ float sh_x[NB*256];
    __shared__ float sh_h[NB][128];

    #pragma unroll
    for (int b=0;b<NB;b++) sh_h[b][hh] = 0.0f;
    float c[NB];
    #pragma unroll
    for (int b=0;b<NB;b++) c[b] = 0.0f;

    const float4* __restrict__ Wx = (const float4*)g_l2_wihT[dir];
    const float4* __restrict__ Wh = (const float4*)g_l2_whhT[dir];
    const float4 bb = ((const float4*)g_l2_b[dir])[hh];

    for (int s=0; s<T_SZ; s++){
        const int t = dir ? (T_SZ-1-s) : s;
        __syncthreads();   // prev-step sh_h writes done; prev sh_x readers done
        const float4* src = (const float4*)(g_h1out + (size_t)t*(B_SZ*256) + (size_t)b0*256);
        #pragma unroll
        for (int i=0;i<8;i++) ((float4*)sh_x)[hh + i*128] = src[hh + i*128];
        __syncthreads();   // sh_x ready

        float4 acc[NB];
        #pragma unroll
        for (int b=0;b<NB;b++) acc[b] = bb;

        #pragma unroll 2
        for (int k=0;k<256;k++){
            float4 w = Wx[k*128 + hh];
            #pragma unroll
            for (int b=0;b<NB;b++){
                float xv = sh_x[b*256 + k];
                acc[b].x = fmaf(xv, w.x, acc[b].x);
                acc[b].y = fmaf(xv, w.y, acc[b].y);
                acc[b].z = fmaf(xv, w.z, acc[b].z);
                acc[b].w = fmaf(xv, w.w, acc[b].w);
            }
        }
        #pragma unroll 2
        for (int k=0;k<128;k++){
            float4 w = Wh[k*128 + hh];
            #pragma unroll
            for (int b=0;b<NB;b++){
                float hv = sh_h[b][k];
                acc[b].x = fmaf(hv, w.x, acc[b].x);
                acc[b].y = fmaf(hv, w.y, acc[b].y);
                acc[b].z = fmaf(hv, w.z, acc[b].z);
                acc[b].w = fmaf(hv, w.w, acc[b].w);
            }
        }
        __syncthreads();   // all sh_h reads done
        #pragma unroll
        for (int b=0;b<NB;b++){
            float ig = sigf(acc[b].x);
            float fg = sigf(acc[b].y);
            float gg = tanhf(acc[b].z);
            float og = sigf(acc[b].w);
            c[b] = fmaf(fg, c[b], ig*gg);
            sh_h[b][hh] = og * tanhf(c[b]);
        }
    }
    __syncthreads();
    #pragma unroll
    for (int b=0;b<NB;b++) g_hn[2+dir][(b0+b)*128 + hh] = sh_h[b][hh];
}

// ---------------- FC head: hidden_lstm (quirky reshape) -> fc1 -> fc2 -> concat emb ----------------
__global__ void __launch_bounds__(256) k_fc(const int* __restrict__ node_data,
                                            const float* __restrict__ emb,
                                            const float* __restrict__ fc1_b,
                                            const float* __restrict__ fc2_b)
{
    const int r = blockIdx.x;       // 0..2047
    const int c = threadIdx.x;      // 0..255
    __shared__ float sh_in[256];
    __shared__ float sh_mid[256];

    // hn.reshape(-1, 256): row r col c = hn[d][2*(r%1024) + c/128][c%128]
    int d = r >> 10;
    int b = ((r & 1023) << 1) + (c >> 7);
    int k = c & 127;
    sh_in[c] = g_hn[d][b*128 + k] + g_hn[2+d][b*128 + k];
    __syncthreads();

    float acc = fc1_b[c];
    #pragma unroll 4
    for (int i=0;i<256;i++) acc = fmaf(sh_in[i], g_fc1_wT[i*256 + c], acc);
    sh_mid[c] = sigf(acc);
    __syncthreads();

    if (c < 64){
        float a2 = fc2_b[c];
        #pragma unroll 4
        for (int i=0;i<256;i++) a2 = fmaf(sh_mid[i], g_fc2_wT[i*64 + c], a2);
        g_hidden[r*128 + c] = sigf(a2);
    } else if (c < 128){
        int e = c - 64;
        int n0 = node_data[r*2], n1 = node_data[r*2+1];
        g_hidden[r*128 + 64 + e] = 0.5f*(emb[n0*64 + e] + emb[n1*64 + e]);
    }
}

// ---------------- decoder: 200 steps of GRU(128) -> GRU(50) -> sigmoid dec ----------------
__global__ void __launch_bounds__(160) k_dec(const float* __restrict__ edge,
                                             const float* __restrict__ g2_bih,
                                             const float* __restrict__ g2_bhh,
                                             const float* __restrict__ dec_w,
                                             const float* __restrict__ dec_b,
                                             float* __restrict__ out)
{
    const int b0  = blockIdx.x * NB;
    const int tid = threadIdx.x;     // 0..159

    __shared__ float sh_h1[2][NB][128];
    __shared__ float sh_h2[NB][52];
    __shared__ float sh_gi[NB][152];
    __shared__ float sh_gh[NB][152];
    __shared__ float sh_res[NB];
    __shared__ float sh_dw[52];

    if (tid < 128){
        #pragma unroll
        for (int b=0;b<NB;b++) sh_h1[0][b][tid] = g_hidden[(b0+b)*128 + tid];
    }
    if (tid < 52){
        #pragma unroll
        for (int b=0;b<NB;b++) sh_h2[b][tid] = 0.0f;
        sh_dw[tid] = (tid < 50) ? dec_w[tid] : 0.0f;
    }
    if (tid < NB) sh_res[tid] = edge[(b0+tid)*T_SZ + (T_SZ-1)];

    float4 wi = {0,0,0,0}, bi = {0,0,0,0}, bh = {0,0,0,0};
    if (tid < 128){
        wi = ((const float4*)g_g1_wih)[tid];
        bi = ((const float4*)g_g1_bih)[tid];
        bh = ((const float4*)g_g1_bhh)[tid];
    }
    float g2bi = 0.0f, g2bh = 0.0f;
    if (tid < 150){ g2bi = g2_bih[tid]; g2bh = g2_bhh[tid]; }
    const float decb = dec_b[0];
    __syncthreads();

    for (int t=0; t<T_SZ; t++){
        const int cur = t & 1, nxt = cur ^ 1;

        // Phase A: GRU1 (128 hidden), thread = hidden index
        if (tid < 128){
            float ax[NB], ay[NB], az[NB];
            #pragma unroll
            for (int b=0;b<NB;b++){ ax[b]=bh.x; ay[b]=bh.y; az[b]=bh.z; }
            const float4* __restrict__ W = (const float4*)g_g1_whhT;
            #pragma unroll 2
            for (int k=0;k<128;k++){
                float4 w = W[k*128 + tid];
                #pragma unroll
                for (int b=0;b<NB;b++){
                    float hv = sh_h1[cur][b][k];
                    ax[b] = fmaf(hv, w.x, ax[b]);
                    ay[b] = fmaf(hv, w.y, ay[b]);
                    az[b] = fmaf(hv, w.z, az[b]);
                }
            }
            #pragma unroll
            for (int b=0;b<NB;b++){
                float res = sh_res[b];
                float ir  = fmaf(res, wi.x, bi.x);
                float iz  = fmaf(res, wi.y, bi.y);
                float inn = fmaf(res, wi.z, bi.z);
                float rg = sigf(ir + ax[b]);
                float zg = sigf(iz + ay[b]);
                float ng = tanhf(fmaf(rg, az[b], inn));
                float h1 = sh_h1[cur][b][tid];
                sh_h1[nxt][b][tid] = fmaf(zg, h1 - ng, ng);   // (1-z)*n + z*h
            }
        }
        __syncthreads();

        // Phase B: GRU2 pre-activations, thread = gate index (150)
        if (tid < 150){
            float gi[NB], gh[NB];
            #pragma unroll
            for (int b=0;b<NB;b++){ gi[b]=g2bi; gh[b]=g2bh; }
            #pragma unroll 2
            for (int k=0;k<128;k++){
                float w = g_g2_wihT[k*160 + tid];
                #pragma unroll
                for (int b=0;b<NB;b++) gi[b] = fmaf(sh_h1[nxt][b][k], w, gi[b]);
            }
            #pragma unroll 2
            for (int k=0;k<50;k++){
                float w = g_g2_whhT[k*160 + tid];
                #pragma unroll
                for (int b=0;b<NB;b++) gh[b] = fmaf(sh_h2[b][k], w, gh[b]);
            }
            #pragma unroll
            for (int b=0;b<NB;b++){ sh_gi[b][tid]=gi[b]; sh_gh[b][tid]=gh[b]; }
        }
        __syncthreads();

        // Phase C: GRU2 combine, thread = h2 index (50)
        if (tid < 50){
            #pragma unroll
            for (int b=0;b<NB;b++){
                float rg = sigf(sh_gi[b][tid]      + sh_gh[b][tid]);
                float zg = sigf(sh_gi[b][50+tid]   + sh_gh[b][50+tid]);
                float ng = tanhf(fmaf(rg, sh_gh[b][100+tid], sh_gi[b][100+tid]));
                float h2 = sh_h2[b][tid];
                sh_h2[b][tid] = fmaf(zg, h2 - ng, ng);
            }
        }
        __syncthreads();

        // Phase D: decoder dot + sigmoid, thread = batch row (16)
        if (tid < NB){
            float s = decb;
            #pragma unroll 2
            for (int k=0;k<50;k++) s = fmaf(sh_h2[tid][k], sh_dw[k], s);
            float r = sigf(s);
            sh_res[tid] = r;
            out[(b0+tid)*T_SZ + t] = r;
        }
        __syncthreads();
    }
}

extern "C" void kernel_launch(void* const* d_in, const int* in_sizes, int n_in,
                              void* d_out, int out_size)
{
    const int*   node_data = (const int*)  d_in[0];
    const float* edge_data = (const float*)d_in[1];
    const float* emb       = (const float*)d_in[2];
    const float* l1_wih_f  = (const float*)d_in[3];
    const float* l1_whh_f  = (const float*)d_in[4];
    const float* l1_b_f    = (const float*)d_in[5];
    const float* l1_wih_b  = (const float*)d_in[6];
    const float* l1_whh_b  = (const float*)d_in[7];
    const float* l1_b_b    = (const float*)d_in[8];
    const float* l2_wih_f  = (const float*)d_in[9];
    const float* l2_whh_f  = (const float*)d_in[10];
    const float* l2_b_f    = (const float*)d_in[11];
    const float* l2_wih_b  = (const float*)d_in[12];
    const float* l2_whh_b  = (const float*)d_in[13];
    const float* l2_b_b    = (const float*)d_in[14];
    const float* fc1_w     = (const float*)d_in[15];
    const float* fc1_b     = (const float*)d_in[16];
    const float* fc2_w     = (const float*)d_in[17];
    const float* fc2_b     = (const float*)d_in[18];
    const float* g1_wih    = (const float*)d_in[19];
    const float* g1_whh    = (const float*)d_in[20];
    const float* g1_bih    = (const float*)d_in[21];
    const float* g1_bhh    = (const float*)d_in[22];
    const float* g2_wih    = (const float*)d_in[23];
    const float* g2_whh    = (const float*)d_in[24];
    const float* g2_bih    = (const float*)d_in[25];
    const float* g2_bhh    = (const float*)d_in[26];
    const float* dec_w     = (const float*)d_in[27];
    const float* dec_b     = (const float*)d_in[28];
    float* out = (float*)d_out;

    k_prep<<<256, 256>>>(l1_wih_f, l1_whh_f, l1_b_f, l1_wih_b, l1_whh_b, l1_b_b,
                         l2_wih_f, l2_whh_f, l2_b_f, l2_wih_b, l2_whh_b, l2_b_b,
                         fc1_w, fc2_w, g1_wih, g1_whh, g1_bih, g1_bhh,
                         g2_wih, g2_whh);
    k_lstm1<<<dim3(B_SZ/NB, 2), 128>>>(edge_data);
    k_lstm2<<<dim3(B_SZ/NB, 2), 128>>>();
    k_fc<<<B_SZ, 256>>>(node_data, emb, fc1_b, fc2_b);
    k_dec<<<B_SZ/NB, 160>>>(edge_data, g2_bih, g2_bhh, dec_w, dec_b, out);
}

// round 9
// speedup vs baseline: 1.4773x; 1.4773x over previous
#include <cuda_runtime.h>
#include <math.h>

#define B_SZ 2048
#define T_SZ 200
#define NB   16

typedef unsigned long long u64;

// ---- packed fp32x2 helpers (SASS FFMA2: only reachable via PTX) ----
__device__ __forceinline__ void ffma2(u64 &d, u64 a, u64 b){
    asm("fma.rn.f32x2 %0, %1, %2, %0;" : "+l"(d) : "l"(a), "l"(b));
}
__device__ __forceinline__ u64 pack2(float lo, float hi){
    u64 r; asm("mov.b64 %0, {%1, %2};" : "=l"(r) : "f"(lo), "f"(hi)); return r;
}
__device__ __forceinline__ float2 unpack2(u64 v){
    float2 r; asm("mov.b64 {%0, %1}, %2;" : "=f"(r.x), "=f"(r.y) : "l"(v)); return r;
}

// ---------------- device scratch (no runtime allocation allowed) ----------------
__device__ __align__(16) float g_l1_whhT[2][128*512];
__device__ __align__(16) float g_l1_wih [2][512];
__device__ __align__(16) float g_l1_b   [2][512];
__device__ __align__(16) float g_l2_wihT[2][256*512];
__device__ __align__(16) float g_l2_whhT[2][128*512];
__device__ __align__(16) float g_l2_b   [2][512];
__device__ __align__(16) float g_fc1_wT[256*256];
__device__ __align__(16) float g_fc2_wT[256*64];
__device__ __align__(16) float g_g1_whhT[128*512];
__device__ __align__(16) float g_g1_wih[512];
__device__ __align__(16) float g_g1_bih[512];
__device__ __align__(16) float g_g1_bhh[512];
__device__ __align__(16) float g_g2_wihT[128*160];
__device__ __align__(16) float g_g2_whhT[50*160];
__device__ __align__(16) float2 g_h1out[(size_t)T_SZ*B_SZ*256]; // [t][b][256], value duplicated {h,h}
__device__ __align__(16) float g_hn[4][B_SZ*128];               // L1 f/b, L2 f/b final h
__device__ __align__(16) float g_hidden[B_SZ*128];              // decoder h1 init

__device__ __forceinline__ float sigf(float x){ return 1.0f/(1.0f + expf(-x)); }

// ---------------- weight permutation ----------------
// Gate-quad layout: transposed weight column (h*4+q) = original gate row (q*H+h).
__global__ void k_prep(
    const float* __restrict__ l1_wih_f, const float* __restrict__ l1_whh_f, const float* __restrict__ l1_b_f,
    const float* __restrict__ l1_wih_b, const float* __restrict__ l1_whh_b, const float* __restrict__ l1_b_b,
    const float* __restrict__ l2_wih_f, const float* __restrict__ l2_whh_f, const float* __restrict__ l2_b_f,
    const float* __restrict__ l2_wih_b, const float* __restrict__ l2_whh_b, const float* __restrict__ l2_b_b,
    const float* __restrict__ fc1_w, const float* __restrict__ fc2_w,
    const float* __restrict__ g1_wih, const float* __restrict__ g1_whh,
    const float* __restrict__ g1_bih, const float* __restrict__ g1_bhh,
    const float* __restrict__ g2_wih, const float* __restrict__ g2_whh)
{
    const int idx = blockIdx.x*blockDim.x + threadIdx.x;
    const int stride = gridDim.x*blockDim.x;

    for (int i=idx; i<2*128*512; i+=stride){          // L1 whh^T
        int dir=i>>16, r=i&65535, k=r>>9, col=r&511, h=col>>2, q=col&3;
        const float* s = dir ? l1_whh_b : l1_whh_f;
        g_l1_whhT[dir][r] = s[(q*128+h)*128 + k];
    }
    for (int i=idx; i<2*128*512; i+=stride){          // L2 whh^T
        int dir=i>>16, r=i&65535, k=r>>9, col=r&511, h=col>>2, q=col&3;
        const float* s = dir ? l2_whh_b : l2_whh_f;
        g_l2_whhT[dir][r] = s[(q*128+h)*128 + k];
    }
    for (int i=idx; i<2*256*512; i+=stride){          // L2 wih^T
        int dir=i>>17, r=i&131071, k=r>>9, col=r&511, h=col>>2, q=col&3;
        const float* s = dir ? l2_wih_b : l2_wih_f;
        g_l2_wihT[dir][r] = s[(q*128+h)*256 + k];
    }
    for (int i=idx; i<2*512; i+=stride){              // small vectors
        int dir=i>>9, col=i&511, h=col>>2, q=col&3, g=q*128+h;
        g_l1_wih[dir][col] = (dir ? l1_wih_b : l1_wih_f)[g];
        g_l1_b  [dir][col] = (dir ? l1_b_b   : l1_b_f  )[g];
        g_l2_b  [dir][col] = (dir ? l2_b_b   : l2_b_f  )[g];
    }
    for (int i=idx; i<256*256; i+=stride){            // fc1^T
        int c=i>>8, j=i&255;
        g_fc1_wT[i] = fc1_w[j*256+c];
    }
    for (int i=idx; i<256*64; i+=stride){             // fc2^T
        int c=i>>6, j=i&63;
        g_fc2_wT[i] = fc2_w[j*256+c];
    }
    for (int i=idx; i<128*512; i+=stride){            // g1 whh^T (3 gates, q=3 padded 0)
        int k=i>>9, col=i&511, h=col>>2, q=col&3;
        g_g1_whhT[i] = (q<3) ? g1_whh[(q*128+h)*128 + k] : 0.0f;
    }
    for (int i=idx; i<512; i+=stride){                // g1 vectors
        int h=i>>2, q=i&3;
        g_g1_wih[i] = (q<3) ? g1_wih[q*128+h] : 0.0f;
        g_g1_bih[i] = (q<3) ? g1_bih[q*128+h] : 0.0f;
        g_g1_bhh[i] = (q<3) ? g1_bhh[q*128+h] : 0.0f;
    }
    for (int i=idx; i<128*160; i+=stride){            // g2 wih^T
        int k=i/160, g=i%160;
        g_g2_wihT[i] = (g<150) ? g2_wih[g*128+k] : 0.0f;
    }
    for (int i=idx; i<50*160; i+=stride){             // g2 whh^T
        int k=i/160, g=i%160;
        g_g2_whhT[i] = (g<150) ? g2_whh[g*50+k] : 0.0f;
    }
}

// ---------------- BiLSTM layer 1 (input dim 1), FFMA2 inner loop ----------------
__global__ void __launch_bounds__(128) k_lstm1(const float* __restrict__ edge)
{
    const int dir = blockIdx.y;
    const int b0  = blockIdx.x * NB;
    const int hh  = threadIdx.x;

    __shared__ float sh_x[NB][T_SZ];
    __shared__ u64   sh_h[NB][128];     // duplicated {h,h}

    for (int i = hh; i < NB*T_SZ; i += 128){
        int b = i / T_SZ, t = i % T_SZ;
        sh_x[b][t] = edge[(b0+b)*T_SZ + t];
    }
    #pragma unroll
    for (int b=0;b<NB;b++) sh_h[b][hh] = 0ull;
    float c[NB];
    #pragma unroll
    for (int b=0;b<NB;b++) c[b] = 0.0f;

    const ulonglong2* __restrict__ W = (const ulonglong2*)g_l1_whhT[dir];
    const u64* wib = (const u64*)g_l1_wih[dir];
    const u64* bbp = (const u64*)g_l1_b[dir];
    const u64 wi01 = wib[2*hh], wi23 = wib[2*hh+1];
    const u64 b01  = bbp[2*hh], b23  = bbp[2*hh+1];
    __syncthreads();

    for (int s=0; s<T_SZ; s++){
        const int t = dir ? (T_SZ-1-s) : s;
        u64 a01[NB], a23[NB];
        #pragma unroll
        for (int b=0;b<NB;b++){
            float xv = sh_x[b][t];
            u64 x2 = pack2(xv, xv);
            a01[b] = b01; ffma2(a01[b], wi01, x2);
            a23[b] = b23; ffma2(a23[b], wi23, x2);
        }
        #pragma unroll 4
        for (int k=0;k<128;k++){
            ulonglong2 w = W[k*128 + hh];
            #pragma unroll
            for (int b=0;b<NB;b++){
                u64 hv = sh_h[b][k];
                ffma2(a01[b], w.x, hv);
                ffma2(a23[b], w.y, hv);
            }
        }
        __syncthreads();
        float2* outp = g_h1out + (size_t)t*(B_SZ*256) + (size_t)b0*256 + dir*128 + hh;
        #pragma unroll
        for (int b=0;b<NB;b++){
            float2 g01 = unpack2(a01[b]);
            float2 g23 = unpack2(a23[b]);
            float ig = sigf(g01.x);
            float fg = sigf(g01.y);
            float gg = tanhf(g23.x);
            float og = sigf(g23.y);
            c[b] = fmaf(fg, c[b], ig*gg);
            float h = og * tanhf(c[b]);
            sh_h[b][hh] = pack2(h, h);
            outp[b*256] = make_float2(h, h);
        }
        __syncthreads();
    }
    #pragma unroll
    for (int b=0;b<NB;b++) g_hn[dir][(b0+b)*128 + hh] = unpack2(sh_h[b][hh]).x;
}

// ---------------- BiLSTM layer 2 (input dim 256 fused), FFMA2 ----------------
__global__ void __launch_bounds__(128) k_lstm2()
{
    const int dir = blockIdx.y;
    const int b0  = blockIdx.x * NB;
    const int hh  = threadIdx.x;

    __shared__ u64 sh_x[NB*256];        // duplicated input pairs
    __shared__ u64 sh_h[NB][128];       // duplicated h pairs

    #pragma unroll
    for (int b=0;b<NB;b++) sh_h[b][hh] = 0ull;
    float c[NB];
    #pragma unroll
    for (int b=0;b<NB;b++) c[b] = 0.0f;

    const ulonglong2* __restrict__ Wx = (const ulonglong2*)g_l2_wihT[dir];
    const ulonglong2* __restrict__ Wh = (const ulonglong2*)g_l2_whhT[dir];
    const u64* bbp = (const u64*)g_l2_b[dir];
    const u64 b01 = bbp[2*hh], b23 = bbp[2*hh+1];

    for (int s=0; s<T_SZ; s++){
        const int t = dir ? (T_SZ-1-s) : s;
        __syncthreads();   // prev sh_h writes done; prev sh_x readers done
        const uint4* __restrict__ src =
            (const uint4*)(g_h1out + (size_t)t*(B_SZ*256) + (size_t)b0*256);
        #pragma unroll
        for (int i=0;i<16;i++) ((uint4*)sh_x)[hh + i*128] = src[hh + i*128];
        __syncthreads();   // sh_x ready

        u64 a01[NB], a23[NB];
        #pragma unroll
        for (int b=0;b<NB;b++){ a01[b] = b01; a23[b] = b23; }

        #pragma unroll 4
        for (int k=0;k<256;k++){
            ulonglong2 w = Wx[k*128 + hh];
            #pragma unroll
            for (int b=0;b<NB;b++){
                u64 xv = sh_x[b*256 + k];
                ffma2(a01[b], w.x, xv);
                ffma2(a23[b], w.y, xv);
            }
        }
        #pragma unroll 4
        for (int k=0;k<128;k++){
            ulonglong2 w = Wh[k*128 + hh];
            #pragma unroll
            for (int b=0;b<NB;b++){
                u64 hv = sh_h[b][k];
                ffma2(a01[b], w.x, hv);
                ffma2(a23[b], w.y, hv);
            }
        }
        __syncthreads();   // all sh_h reads done
        #pragma unroll
        for (int b=0;b<NB;b++){
            float2 g01 = unpack2(a01[b]);
            float2 g23 = unpack2(a23[b]);
            float ig = sigf(g01.x);
            float fg = sigf(g01.y);
            float gg = tanhf(g23.x);
            float og = sigf(g23.y);
            c[b] = fmaf(fg, c[b], ig*gg);
            float h = og * tanhf(c[b]);
            sh_h[b][hh] = pack2(h, h);
        }
    }
    __syncthreads();
    #pragma unroll
    for (int b=0;b<NB;b++) g_hn[2+dir][(b0+b)*128 + hh] = unpack2(sh_h[b][hh]).x;
}

// ---------------- FC head ----------------
__global__ void __launch_bounds__(256) k_fc(const int* __restrict__ node_data,
                                            const float* __restrict__ emb,
                                            const float* __restrict__ fc1_b,
                                            const float* __restrict__ fc2_b)
{
    const int r = blockIdx.x;       // 0..2047
    const int c = threadIdx.x;      // 0..255
    __shared__ float sh_in[256];
    __shared__ float sh_mid[256];

    // hn.reshape(-1, 256): row r col c = hn[d][2*(r%1024) + c/128][c%128]
    int d = r >> 10;
    int b = ((r & 1023) << 1) + (c >> 7);
    int k = c & 127;
    sh_in[c] = g_hn[d][b*128 + k] + g_hn[2+d][b*128 + k];
    __syncthreads();

    float acc = fc1_b[c];
    #pragma unroll 4
    for (int i=0;i<256;i++) acc = fmaf(sh_in[i], g_fc1_wT[i*256 + c], acc);
    sh_mid[c] = sigf(acc);
    __syncthreads();

    if (c < 64){
        float a2 = fc2_b[c];
        #pragma unroll 4
        for (int i=0;i<256;i++) a2 = fmaf(sh_mid[i], g_fc2_wT[i*64 + c], a2);
        g_hidden[r*128 + c] = sigf(a2);
    } else if (c < 128){
        int e = c - 64;
        int n0 = node_data[r*2], n1 = node_data[r*2+1];
        g_hidden[r*128 + 64 + e] = 0.5f*(emb[n0*64 + e] + emb[n1*64 + e]);
    }
}

// ---------------- decoder: GRU(128) -> GRU(50) -> sigmoid, 200 steps ----------------
__global__ void __launch_bounds__(160) k_dec(const float* __restrict__ edge,
                                             const float* __restrict__ g2_bih,
                                             const float* __restrict__ g2_bhh,
                                             const float* __restrict__ dec_w,
                                             const float* __restrict__ dec_b,
                                             float* __restrict__ out)
{
    const int b0  = blockIdx.x * NB;
    const int tid = threadIdx.x;     // 0..159

    __shared__ float sh_h1[2][NB][128];
    __shared__ float sh_h2[NB][52];
    __shared__ float sh_s  [NB][100];   // r/z gate sums (gi+gh)
    __shared__ float sh_inn[NB][52];    // n-gate input part
    __shared__ float sh_hn [NB][52];    // n-gate hidden part
    __shared__ float sh_res[NB];
    __shared__ float sh_dw[52];

    if (tid < 128){
        #pragma unroll
        for (int b=0;b<NB;b++) sh_h1[0][b][tid] = g_hidden[(b0+b)*128 + tid];
    }
    if (tid < 52){
        #pragma unroll
        for (int b=0;b<NB;b++) sh_h2[b][tid] = 0.0f;
        sh_dw[tid] = (tid < 50) ? dec_w[tid] : 0.0f;
    }
    if (tid < NB) sh_res[tid] = edge[(b0+tid)*T_SZ + (T_SZ-1)];

    float4 wi = {0,0,0,0}, bi = {0,0,0,0}, bh = {0,0,0,0};
    if (tid < 128){
        wi = ((const float4*)g_g1_wih)[tid];
        bi = ((const float4*)g_g1_bih)[tid];
        bh = ((const float4*)g_g1_bhh)[tid];
    }
    float g2bi = 0.0f, g2bh = 0.0f;
    if (tid < 150){ g2bi = g2_bih[tid]; g2bh = g2_bhh[tid]; }
    const float decb = dec_b[0];
    __syncthreads();

    for (int t=0; t<T_SZ; t++){
        const int cur = t & 1, nxt = cur ^ 1;

        // Phase A: GRU1 (128 hidden), gate pairs (r,z),(n,pad) via FFMA2
        if (tid < 128){
            u64 a01[NB], a23[NB];
            const u64 bh01 = pack2(bh.x, bh.y);
            const u64 bh23 = pack2(bh.z, bh.w);
            #pragma unroll
            for (int b=0;b<NB;b++){ a01[b] = bh01; a23[b] = bh23; }
            const ulonglong2* __restrict__ W = (const ulonglong2*)g_g1_whhT;
            #pragma unroll 4
            for (int k=0;k<128;k++){
                ulonglong2 w = W[k*128 + tid];
                #pragma unroll
                for (int b=0;b<NB;b++){
                    float hv = sh_h1[cur][b][k];
                    u64 hv2 = pack2(hv, hv);
                    ffma2(a01[b], w.x, hv2);
                    ffma2(a23[b], w.y, hv2);
                }
            }
            #pragma unroll
            for (int b=0;b<NB;b++){
                float2 g01 = unpack2(a01[b]);
                float2 g23 = unpack2(a23[b]);
                float res = sh_res[b];
                float ir  = fmaf(res, wi.x, bi.x);
                float iz  = fmaf(res, wi.y, bi.y);
                float inn = fmaf(res, wi.z, bi.z);
                float rg = sigf(ir + g01.x);
                float zg = sigf(iz + g01.y);
                float ng = tanhf(fmaf(rg, g23.x, inn));
                float h1 = sh_h1[cur][b][tid];
                sh_h1[nxt][b][tid] = fmaf(zg, h1 - ng, ng);
            }
        }
        __syncthreads();

        // Phase B: GRU2 pre-activations, thread = gate index (150)
        if (tid < 150){
            float gi[NB], gh[NB];
            #pragma unroll
            for (int b=0;b<NB;b++){ gi[b]=g2bi; gh[b]=g2bh; }
            #pragma unroll 4
            for (int k=0;k<128;k++){
                float w = g_g2_wihT[k*160 + tid];
                #pragma unroll
                for (int b=0;b<NB;b++) gi[b] = fmaf(sh_h1[nxt][b][k], w, gi[b]);
            }
            #pragma unroll 2
            for (int k=0;k<50;k++){
                float w = g_g2_whhT[k*160 + tid];
                #pragma unroll
                for (int b=0;b<NB;b++) gh[b] = fmaf(sh_h2[b][k], w, gh[b]);
            }
            if (tid < 100){
                #pragma unroll
                for (int b=0;b<NB;b++) sh_s[b][tid] = gi[b] + gh[b];
            } else {
                #pragma unroll
                for (int b=0;b<NB;b++){ sh_inn[b][tid-100]=gi[b]; sh_hn[b][tid-100]=gh[b]; }
            }
        }
        __syncthreads();

        // Phase C: GRU2 combine, thread = h2 index (50)
        if (tid < 50){
            #pragma unroll
            for (int b=0;b<NB;b++){
                float rg = sigf(sh_s[b][tid]);
                float zg = sigf(sh_s[b][50+tid]);
                float ng = tanhf(fmaf(rg, sh_hn[b][tid], sh_inn[b][tid]));
                float h2 = sh_h2[b][tid];
                sh_h2[b][tid] = fmaf(zg, h2 - ng, ng);
            }
        }
        __syncthreads();

        // Phase D: decoder dot + sigmoid, thread = batch row (16)
        if (tid < NB){
            float s = decb;
            #pragma unroll 2
            for (int k=0;k<50;k++) s = fmaf(sh_h2[tid][k], sh_dw[k], s);
            float r = sigf(s);
            sh_res[tid] = r;
            out[(b0+tid)*T_SZ + t] = r;
        }
        __syncthreads();
    }
}

extern "C" void kernel_launch(void* const* d_in, const int* in_sizes, int n_in,
                              void* d_out, int out_size)
{
    const int*   node_data = (const int*)  d_in[0];
    const float* edge_data = (const float*)d_in[1];
    const float* emb       = (const float*)d_in[2];
    const float* l1_wih_f  = (const float*)d_in[3];
    const float* l1_whh_f  = (const float*)d_in[4];
    const float* l1_b_f    = (const float*)d_in[5];
    const float* l1_wih_b  = (const float*)d_in[6];
    const float* l1_whh_b  = (const float*)d_in[7];
    const float* l1_b_b    = (const float*)d_in[8];
    const float* l2_wih_f  = (const float*)d_in[9];
    const float* l2_whh_f  = (const float*)d_in[10];
    const float* l2_b_f    = (const float*)d_in[11];
    const float* l2_wih_b  = (const float*)d_in[12];
    const float* l2_whh_b  = (const float*)d_in[13];
    const float* l2_b_b    = (const float*)d_in[14];
    const float* fc1_w     = (const float*)d_in[15];
    const float* fc1_b     = (const float*)d_in[16];
    const float* fc2_w     = (const float*)d_in[17];
    const float* fc2_b     = (const float*)d_in[18];
    const float* g1_wih    = (const float*)d_in[19];
    const float* g1_whh    = (const float*)d_in[20];
    const float* g1_bih    = (const float*)d_in[21];
    const float* g1_bhh    = (const float*)d_in[22];
    const float* g2_wih    = (const float*)d_in[23];
    const float* g2_whh    = (const float*)d_in[24];
    const float* g2_bih    = (const float*)d_in[25];
    const float* g2_bhh    = (const float*)d_in[26];
    const float* dec_w     = (const float*)d_in[27];
    const float* dec_b     = (const float*)d_in[28];
    float* out = (float*)d_out;

    k_prep<<<256, 256>>>(l1_wih_f, l1_whh_f, l1_b_f, l1_wih_b, l1_whh_b, l1_b_b,
                         l2_wih_f, l2_whh_f, l2_b_f, l2_wih_b, l2_whh_b, l2_b_b,
                         fc1_w, fc2_w, g1_wih, g1_whh, g1_bih, g1_bhh,
                         g2_wih, g2_whh);
    k_lstm1<<<dim3(B_SZ/NB, 2), 128>>>(edge_data);
    k_lstm2<<<dim3(B_SZ/NB, 2), 128>>>();
    k_fc<<<B_SZ, 256>>>(node_data, emb, fc1_b, fc2_b);
    k_dec<<<B_SZ/NB, 160>>>(edge_data, g2_bih, g2_bhh, dec_w, dec_b, out);
}